// round 16
// baseline (speedup 1.0000x reference)
#include <cuda_runtime.h>
#include <cuda_bf16.h>

// VanillaRNN: h_{t+1} = tanh(fma(x_t,Win, h_t@Whh) + bh), 127 steps; out = h@Wout + bout.
// B=2048, T=128, H=512, C=10.
//
// BIT-EXACT arithmetic (rel_err == 0.0 five times, FROZEN):
//  - h@Whh: single-accumulator IEEE-RN FMA chain per (b,j), ascending k
//  - elementwise: s = fma(x, Win, dot) + bh
//  - tanh: XLA EmitFastTanh with_fma: clamp +/-7.99881172180175781, FMA Horner,
//    num = x*p, IEEE div, |x|<0.0004 -> x
//
// Perf structure (R6):
//  - BT=14, grid=147 -> all 147/148 SMs work, per-SMSP floor 56 cyc/k (was 64).
//    Tail CTA clamps batch rows to 2047 (duplicates computed, never stored).
//  - distance-1 register pipeline of the h-row LDS (load row k+1 while fma2
//    row k) — removes the LDS->FMA latency exposure behind the 48% issue.
//  - double-buffered h state in dynamic smem (72 KB): ONE barrier per step.
//  - weight prefetch (dist-1 block double buffer) retained; FFMA2 retained.

#define BB 2048
#define TT 128
#define HH 512
#define CC 10
#define BT 14
#define BTP 16          // padded h-row (64B) for aligned LDS.128
#define NCTA 147
#define NTHREADS 256

typedef unsigned long long ull;

__device__ __forceinline__ void fma2(ull& acc, ull h2, ull w2) {
    // two independent fp32 RN FMAs (lanewise identical to scalar fmaf chains)
    asm("fma.rn.f32x2 %0, %1, %2, %0;" : "+l"(acc) : "l"(h2), "l"(w2));
}
__device__ __forceinline__ ull dup2(float w) {
    ull r; asm("mov.b64 %0, {%1, %1};" : "=l"(r) : "f"(w)); return r;
}
__device__ __forceinline__ void unpack2(float& lo, float& hi, ull v) {
    asm("mov.b64 {%0, %1}, %2;" : "=f"(lo), "=f"(hi) : "l"(v));
}

// XLA llvm_ir EmitFastTanh(with_fma=true) — exact semantics (frozen).
__device__ __forceinline__ float tanh_xla_fma(float a_x) {
    const float kClamp = 7.99881172180175781f;
    float x = fminf(fmaxf(a_x, -kClamp), kClamp);
    float x2 = __fmul_rn(x, x);
    float p = fmaf(x2, -2.76076847742355e-16f, 2.00018790482477e-13f);
    p = fmaf(x2, p, -8.60467152213735e-11f);
    p = fmaf(x2, p,  5.12229709037114e-08f);
    p = fmaf(x2, p,  1.48572235717979e-05f);
    p = fmaf(x2, p,  6.37261928875436e-04f);
    p = fmaf(x2, p,  4.89352455891786e-03f);
    p = __fmul_rn(x, p);
    float q = fmaf(x2, 1.19825839466702e-06f, 1.18534705686654e-04f);
    q = fmaf(x2, q, 2.26843463243900e-03f);
    q = fmaf(x2, q, 4.89352518554385e-03f);
    float r = __fdiv_rn(p, q);
    return (fabsf(a_x) < 0.0004f) ? a_x : r;
}

// load h row k (14 floats = 7 packed pairs): 3x LDS.128 + 1x LDS.64, broadcast
#define LOADROW(dst, hc, k) do {                                               \
    const ulonglong2* _p = reinterpret_cast<const ulonglong2*>((hc) + (k) * BTP); \
    ulonglong2 _v0 = _p[0], _v1 = _p[1], _v2 = _p[2];                          \
    (dst)[0] = _v0.x; (dst)[1] = _v0.y; (dst)[2] = _v1.x; (dst)[3] = _v1.y;    \
    (dst)[4] = _v2.x; (dst)[5] = _v2.y;                                        \
    (dst)[6] = *reinterpret_cast<const ull*>((hc) + (k) * BTP + 12);           \
} while (0)

// 14 packed FMAs for one k-row: cols (j0, j1) against 7 h-pairs
#define FMAROW(a0, a1, hr, wv) do {                                            \
    const ull _wp0 = dup2((wv).x);                                             \
    const ull _wp1 = dup2((wv).y);                                             \
    _Pragma("unroll")                                                          \
    for (int _j = 0; _j < 7; ++_j) fma2((a0)[_j], (hr)[_j], _wp0);             \
    _Pragma("unroll")                                                          \
    for (int _j = 0; _j < 7; ++_j) fma2((a1)[_j], (hr)[_j], _wp1);             \
} while (0)

extern __shared__ float sm_dyn[];

__global__ __launch_bounds__(NTHREADS, 1)
void vanilla_rnn_kernel(const float* __restrict__ x,     // [B, T]
                        const float* __restrict__ Win,   // [1, H]
                        const float* __restrict__ Whh,   // [H, H]
                        const float* __restrict__ bh,    // [H]
                        const float* __restrict__ Wout,  // [H, C]
                        const float* __restrict__ bout,  // [C]
                        float* __restrict__ out)         // [B, C]
{
    float* h0 = sm_dyn;                  // [HH][BTP]  32 KB
    float* h1 = sm_dyn + HH * BTP;       // [HH][BTP]  32 KB
    float* xs = sm_dyn + 2 * HH * BTP;   // [TT][BT]    7 KB

    const int tid = threadIdx.x;
    const int j0  = 2 * tid;             // adjacent hidden columns per thread
    const int j1  = 2 * tid + 1;
    const int b0  = blockIdx.x * BT;

    // init h(buffer 0) = 0 (incl. padding lanes)
    for (int i = tid; i < HH * BTP; i += NTHREADS) h0[i] = 0.0f;
    // stage x transposed with batch-row clamp: xs[t][b] = x[min(b0+b, BB-1)][t]
    for (int i = tid; i < TT * BT; i += NTHREADS) {
        const int t = i / BT, b = i % BT;
        const int bg = min(b0 + b, BB - 1);
        xs[t * BT + b] = x[bg * TT + t];
    }

    const float win_j0 = Win[j0], bh_j0 = bh[j0];
    const float win_j1 = Win[j1], bh_j1 = bh[j1];

    // Whh viewed as [512 rows][256 float2]; this thread reads column pair tid.
    const float2* W2 = reinterpret_cast<const float2*>(Whh);

    __syncthreads();

    for (int t = 0; t < TT - 1; ++t) {
        const float* hc = (t & 1) ? h1 : h0;   // read buffer
        float*       hn = (t & 1) ? h0 : h1;   // write buffer

        ull a0[7], a1[7];
        #pragma unroll
        for (int i = 0; i < 7; ++i) { a0[i] = 0ull; a1[i] = 0ull; }

        // weight double buffer (block dist-1) + h-row pipeline (row dist-1)
        float2 wA[8], wB[8];
        #pragma unroll
        for (int i = 0; i < 8; ++i) wA[i] = W2[i * (HH / 2) + tid];     // blk 0

        ull hP[7];
        LOADROW(hP, hc, 0);

        #pragma unroll 1
        for (int blk = 0; blk < 64; blk += 2) {
            #pragma unroll
            for (int i = 0; i < 8; ++i)
                wB[i] = W2[((blk + 1) * 8 + i) * (HH / 2) + tid];
            #pragma unroll
            for (int i = 0; i < 8; ++i) {
                ull hC[7];
                #pragma unroll
                for (int j = 0; j < 7; ++j) hC[j] = hP[j];
                const int nk = (blk * 8 + i + 1) & (HH - 1);   // wrap: row 0 re-read
                LOADROW(hP, hc, nk);
                FMAROW(a0, a1, hC, wA[i]);
            }
            const int nb = (blk + 2) & 63;                     // wrap: blk 0 re-read
            #pragma unroll
            for (int i = 0; i < 8; ++i)
                wA[i] = W2[(nb * 8 + i) * (HH / 2) + tid];
            #pragma unroll
            for (int i = 0; i < 8; ++i) {
                ull hC[7];
                #pragma unroll
                for (int j = 0; j < 7; ++j) hC[j] = hP[j];
                const int nk = ((blk + 1) * 8 + i + 1) & (HH - 1);
                LOADROW(hP, hc, nk);
                FMAROW(a0, a1, hC, wB[i]);
            }
        }

        // epilogue: bit-exact elementwise; vectorized writes into hn
        {
            const float* xr = xs + t * BT;
            float hv[BT];
            #pragma unroll
            for (int i = 0; i < 7; ++i) {
                float alo, ahi; unpack2(alo, ahi, a0[i]);
                float s0 = __fadd_rn(fmaf(xr[2 * i + 0], win_j0, alo), bh_j0);
                float s1 = __fadd_rn(fmaf(xr[2 * i + 1], win_j0, ahi), bh_j0);
                hv[2 * i + 0] = tanh_xla_fma(s0);
                hv[2 * i + 1] = tanh_xla_fma(s1);
            }
            float* d0 = hn + j0 * BTP;
            reinterpret_cast<float4*>(d0)[0] = make_float4(hv[0], hv[1], hv[2],  hv[3]);
            reinterpret_cast<float4*>(d0)[1] = make_float4(hv[4], hv[5], hv[6],  hv[7]);
            reinterpret_cast<float4*>(d0)[2] = make_float4(hv[8], hv[9], hv[10], hv[11]);
            *reinterpret_cast<float2*>(d0 + 12) = make_float2(hv[12], hv[13]);

            #pragma unroll
            for (int i = 0; i < 7; ++i) {
                float alo, ahi; unpack2(alo, ahi, a1[i]);
                float s0 = __fadd_rn(fmaf(xr[2 * i + 0], win_j1, alo), bh_j1);
                float s1 = __fadd_rn(fmaf(xr[2 * i + 1], win_j1, ahi), bh_j1);
                hv[2 * i + 0] = tanh_xla_fma(s0);
                hv[2 * i + 1] = tanh_xla_fma(s1);
            }
            float* d1 = hn + j1 * BTP;
            reinterpret_cast<float4*>(d1)[0] = make_float4(hv[0], hv[1], hv[2],  hv[3]);
            reinterpret_cast<float4*>(d1)[1] = make_float4(hv[4], hv[5], hv[6],  hv[7]);
            reinterpret_cast<float4*>(d1)[2] = make_float4(hv[8], hv[9], hv[10], hv[11]);
            *reinterpret_cast<float2*>(d1 + 12) = make_float2(hv[12], hv[13]);
        }
        __syncthreads();   // ONE barrier/step: hn visible AND hc reads done
    }

    // final h is in buffer (TT-1)&1 = 1
    const float* hf = h1;
    if (tid < BT * CC) {
        const int b = tid / CC;
        const int c = tid % CC;
        if (b0 + b < BB) {
            float s = 0.0f;
            #pragma unroll 8
            for (int jj = 0; jj < HH; ++jj)
                s = fmaf(hf[jj * BTP + b], Wout[jj * CC + c], s);
            out[(b0 + b) * CC + c] = __fadd_rn(s, bout[c]);
        }
    }
}

extern "C" void kernel_launch(void* const* d_in, const int* in_sizes, int n_in,
                              void* d_out, int out_size)
{
    // dict order: x, Win, Whh, bh, Wout, bout; defensive remap if alphabetical.
    int ix = 0, iwin = 1, iwhh = 2, ibh = 3, iwout = 4, ibout = 5;
    if (n_in == 6 && in_sizes[2] == 5120) {
        iwhh = 0; iwin = 1; iwout = 2; ibh = 3; ibout = 4; ix = 5;
    }

    const float* x    = (const float*)d_in[ix];
    const float* Win  = (const float*)d_in[iwin];
    const float* Whh  = (const float*)d_in[iwhh];
    const float* bh   = (const float*)d_in[ibh];
    const float* Wout = (const float*)d_in[iwout];
    const float* bout = (const float*)d_in[ibout];
    float* out = (float*)d_out;

    const int smem_bytes = (2 * HH * BTP + TT * BT) * sizeof(float);  // 72704
    static int attr_set = 0;
    if (!attr_set) {
        cudaFuncSetAttribute(vanilla_rnn_kernel,
                             cudaFuncAttributeMaxDynamicSharedMemorySize,
                             smem_bytes);
        attr_set = 1;
    }

    dim3 grid(NCTA);         // 147 CTAs: ceil(2048/14), tail rows clamped
    dim3 block(NTHREADS);    // 256 threads, 2 adjacent hidden columns each
    vanilla_rnn_kernel<<<grid, block, smem_bytes>>>(x, Win, Whh, bh, Wout, bout, out);
}

// round 17
// speedup vs baseline: 1.1870x; 1.1870x over previous
#include <cuda_runtime.h>
#include <cuda_bf16.h>

// VanillaRNN: h_{t+1} = tanh(fma(x_t,Win, h_t@Whh) + bh), 127 steps; out = h@Wout + bout.
// B=2048, T=128, H=512, C=10.
//
// BIT-EXACT arithmetic (rel_err == 0.0 six times, FROZEN):
//  - h@Whh: single-accumulator IEEE-RN FMA chain per (b,j), ascending k
//  - elementwise: s = fma(x, Win, dot) + bh
//  - tanh: XLA EmitFastTanh with_fma: clamp +/-7.99881172180175781, FMA Horner,
//    num = x*p, IEEE div, |x|<0.0004 -> x
//
// Perf structure (R7) = R14's clean blocks + R15's good parts only:
//  - BT=14, grid=147: floor 56 cyc/k per SMSP, 147/148 SMs busy (tail clamped)
//  - double-buffered h in dynamic smem (72.7 KB): ONE barrier per step
//  - weight double-buffer with wA hoisted across steps: the blk-wrap load
//    prefetches next step's first block BEFORE the barrier (hidden by epilogue)
//  - NO manual h-row pipeline / register copies (R15's regression cause)

#define BB 2048
#define TT 128
#define HH 512
#define CC 10
#define BT 14
#define BTP 16          // padded h row (64B) for aligned LDS.128
#define NCTA 147
#define NTHREADS 256

typedef unsigned long long ull;

__device__ __forceinline__ void fma2(ull& acc, ull h2, ull w2) {
    // two independent fp32 RN FMAs (lanewise identical to scalar fmaf chains)
    asm("fma.rn.f32x2 %0, %1, %2, %0;" : "+l"(acc) : "l"(h2), "l"(w2));
}
__device__ __forceinline__ ull dup2(float w) {
    ull r; asm("mov.b64 %0, {%1, %1};" : "=l"(r) : "f"(w)); return r;
}
__device__ __forceinline__ void unpack2(float& lo, float& hi, ull v) {
    asm("mov.b64 {%0, %1}, %2;" : "=f"(lo), "=f"(hi) : "l"(v));
}

// XLA llvm_ir EmitFastTanh(with_fma=true) — exact semantics (frozen).
__device__ __forceinline__ float tanh_xla_fma(float a_x) {
    const float kClamp = 7.99881172180175781f;
    float x = fminf(fmaxf(a_x, -kClamp), kClamp);
    float x2 = __fmul_rn(x, x);
    float p = fmaf(x2, -2.76076847742355e-16f, 2.00018790482477e-13f);
    p = fmaf(x2, p, -8.60467152213735e-11f);
    p = fmaf(x2, p,  5.12229709037114e-08f);
    p = fmaf(x2, p,  1.48572235717979e-05f);
    p = fmaf(x2, p,  6.37261928875436e-04f);
    p = fmaf(x2, p,  4.89352455891786e-03f);
    p = __fmul_rn(x, p);
    float q = fmaf(x2, 1.19825839466702e-06f, 1.18534705686654e-04f);
    q = fmaf(x2, q, 2.26843463243900e-03f);
    q = fmaf(x2, q, 4.89352518554385e-03f);
    float r = __fdiv_rn(p, q);
    return (fabsf(a_x) < 0.0004f) ? a_x : r;
}

// one unroll-8 compute block: k = blk*8 .. blk*8+7 (R14-style, no pipeline)
__device__ __forceinline__ void compute_block(
    const float2 wb[8], const float* hc, int blk,
    ull a0[7], ull a1[7])
{
    #pragma unroll
    for (int i = 0; i < 8; ++i) {
        const int k = blk * 8 + i;
        const ull wp0 = dup2(wb[i].x);
        const ull wp1 = dup2(wb[i].y);
        const float* row = hc + k * BTP;
        ulonglong2 v0 = reinterpret_cast<const ulonglong2*>(row)[0];  // b 0..3
        ulonglong2 v1 = reinterpret_cast<const ulonglong2*>(row)[1];  // b 4..7
        ulonglong2 v2 = reinterpret_cast<const ulonglong2*>(row)[2];  // b 8..11
        ull        v3 = *reinterpret_cast<const ull*>(row + 12);      // b 12..13
        fma2(a0[0], v0.x, wp0);  fma2(a0[1], v0.y, wp0);
        fma2(a0[2], v1.x, wp0);  fma2(a0[3], v1.y, wp0);
        fma2(a0[4], v2.x, wp0);  fma2(a0[5], v2.y, wp0);
        fma2(a0[6], v3,   wp0);
        fma2(a1[0], v0.x, wp1);  fma2(a1[1], v0.y, wp1);
        fma2(a1[2], v1.x, wp1);  fma2(a1[3], v1.y, wp1);
        fma2(a1[4], v2.x, wp1);  fma2(a1[5], v2.y, wp1);
        fma2(a1[6], v3,   wp1);
    }
}

extern __shared__ float sm_dyn[];

__global__ __launch_bounds__(NTHREADS, 1)
void vanilla_rnn_kernel(const float* __restrict__ x,     // [B, T]
                        const float* __restrict__ Win,   // [1, H]
                        const float* __restrict__ Whh,   // [H, H]
                        const float* __restrict__ bh,    // [H]
                        const float* __restrict__ Wout,  // [H, C]
                        const float* __restrict__ bout,  // [C]
                        float* __restrict__ out)         // [B, C]
{
    float* h0 = sm_dyn;                  // [HH][BTP]  32 KB
    float* h1 = sm_dyn + HH * BTP;       // [HH][BTP]  32 KB
    float* xs = sm_dyn + 2 * HH * BTP;   // [TT][BT]  7 KB

    const int tid = threadIdx.x;
    const int j0  = 2 * tid;             // adjacent hidden columns per thread
    const int j1  = 2 * tid + 1;
    const int b0  = blockIdx.x * BT;

    // init h(buffer 0) = 0 (incl. padding lanes)
    for (int i = tid; i < HH * BTP; i += NTHREADS) h0[i] = 0.0f;
    // stage x transposed with tail clamp: xs[t][b] = x[min(b0+b, BB-1)][t]
    for (int i = tid; i < TT * BT; i += NTHREADS) {
        const int t = i / BT, b = i % BT;
        const int bg = min(b0 + b, BB - 1);
        xs[t * BT + b] = x[bg * TT + t];
    }

    const float win_j0 = Win[j0], bh_j0 = bh[j0];
    const float win_j1 = Win[j1], bh_j1 = bh[j1];

    // Whh viewed as [512 rows][256 float2]; this thread reads column pair tid.
    const float2* W2 = reinterpret_cast<const float2*>(Whh);

    // wA persists ACROSS steps: loaded here once, then refilled by the wrap
    // load inside the k-loop (prefetches next step's block 0 pre-barrier).
    float2 wA[8], wB[8];
    #pragma unroll
    for (int i = 0; i < 8; ++i) wA[i] = W2[i * (HH / 2) + tid];

    __syncthreads();

    for (int t = 0; t < TT - 1; ++t) {
        const float* hc = (t & 1) ? h1 : h0;   // read buffer
        float*       hn = (t & 1) ? h0 : h1;   // write buffer

        ull a0[7], a1[7];
        #pragma unroll
        for (int i = 0; i < 7; ++i) { a0[i] = 0ull; a1[i] = 0ull; }

        #pragma unroll 1
        for (int blk = 0; blk < 64; blk += 2) {
            #pragma unroll
            for (int i = 0; i < 8; ++i)
                wB[i] = W2[((blk + 1) * 8 + i) * (HH / 2) + tid];
            compute_block(wA, hc, blk, a0, a1);

            const int nb = (blk + 2) & 63;     // blk=62 -> 0: next step's prefetch
            #pragma unroll
            for (int i = 0; i < 8; ++i)
                wA[i] = W2[(nb * 8 + i) * (HH / 2) + tid];
            compute_block(wB, hc, blk + 1, a0, a1);
        }

        // epilogue: bit-exact elementwise; vectorized writes into hn
        {
            const float* xr = xs + t * BT;
            float hv[BT];
            #pragma unroll
            for (int i = 0; i < 7; ++i) {
                float alo, ahi; unpack2(alo, ahi, a0[i]);
                float s0 = __fadd_rn(fmaf(xr[2 * i + 0], win_j0, alo), bh_j0);
                float s1 = __fadd_rn(fmaf(xr[2 * i + 1], win_j0, ahi), bh_j0);
                hv[2 * i + 0] = tanh_xla_fma(s0);
                hv[2 * i + 1] = tanh_xla_fma(s1);
            }
            float* d0 = hn + j0 * BTP;
            reinterpret_cast<float4*>(d0)[0] = make_float4(hv[0], hv[1], hv[2],  hv[3]);
            reinterpret_cast<float4*>(d0)[1] = make_float4(hv[4], hv[5], hv[6],  hv[7]);
            reinterpret_cast<float4*>(d0)[2] = make_float4(hv[8], hv[9], hv[10], hv[11]);
            *reinterpret_cast<float2*>(d0 + 12) = make_float2(hv[12], hv[13]);

            #pragma unroll
            for (int i = 0; i < 7; ++i) {
                float alo, ahi; unpack2(alo, ahi, a1[i]);
                float s0 = __fadd_rn(fmaf(xr[2 * i + 0], win_j1, alo), bh_j1);
                float s1 = __fadd_rn(fmaf(xr[2 * i + 1], win_j1, ahi), bh_j1);
                hv[2 * i + 0] = tanh_xla_fma(s0);
                hv[2 * i + 1] = tanh_xla_fma(s1);
            }
            float* d1 = hn + j1 * BTP;
            reinterpret_cast<float4*>(d1)[0] = make_float4(hv[0], hv[1], hv[2],  hv[3]);
            reinterpret_cast<float4*>(d1)[1] = make_float4(hv[4], hv[5], hv[6],  hv[7]);
            reinterpret_cast<float4*>(d1)[2] = make_float4(hv[8], hv[9], hv[10], hv[11]);
            *reinterpret_cast<float2*>(d1 + 12) = make_float2(hv[12], hv[13]);
        }
        __syncthreads();   // ONE barrier/step: hn visible AND hc reads done
    }

    // final h is in buffer written at t = TT-2 (even) -> h1
    const float* hf = h1;
    if (tid < BT * CC) {
        const int b = tid / CC;
        const int c = tid % CC;
        if (b0 + b < BB) {
            float s = 0.0f;
            #pragma unroll 8
            for (int jj = 0; jj < HH; ++jj)
                s = fmaf(hf[jj * BTP + b], Wout[jj * CC + c], s);
            out[(b0 + b) * CC + c] = __fadd_rn(s, bout[c]);
        }
    }
}

extern "C" void kernel_launch(void* const* d_in, const int* in_sizes, int n_in,
                              void* d_out, int out_size)
{
    // dict order: x, Win, Whh, bh, Wout, bout; defensive remap if alphabetical.
    int ix = 0, iwin = 1, iwhh = 2, ibh = 3, iwout = 4, ibout = 5;
    if (n_in == 6 && in_sizes[2] == 5120) {
        iwhh = 0; iwin = 1; iwout = 2; ibh = 3; ibout = 4; ix = 5;
    }

    const float* x    = (const float*)d_in[ix];
    const float* Win  = (const float*)d_in[iwin];
    const float* Whh  = (const float*)d_in[iwhh];
    const float* bh   = (const float*)d_in[ibh];
    const float* Wout = (const float*)d_in[iwout];
    const float* bout = (const float*)d_in[ibout];
    float* out = (float*)d_out;

    const int smem_bytes = (2 * HH * BTP + TT * BT) * sizeof(float);  // 72704
    static int attr_set = 0;
    if (!attr_set) {
        cudaFuncSetAttribute(vanilla_rnn_kernel,
                             cudaFuncAttributeMaxDynamicSharedMemorySize,
                             smem_bytes);
        attr_set = 1;
    }

    dim3 grid(NCTA);         // 147 CTAs: ceil(2048/14), tail rows clamped
    dim3 block(NTHREADS);    // 256 threads, 2 adjacent hidden columns each
    vanilla_rnn_kernel<<<grid, block, smem_bytes>>>(x, Win, Whh, bh, Wout, bout, out);
}